// round 14
// baseline (speedup 1.0000x reference)
#include <cuda_runtime.h>
#include <cuda_fp16.h>
#include <cstdint>
#include <cstddef>

// Problem constants
#define BB 4096
#define DD 4096
#define HH 2048
#define TT 8
#define MM 6

#define GAP_THR 1e-4f

// Scratch (device globals)
__device__ float g_h[(size_t)BB * HH];
__device__ float g_xs[(size_t)BB * DD];
__device__ float g_wc[(size_t)HH * 48];   // W2 @ Ws
__device__ float g_bc[48];                // b2 @ Ws + bs
__device__ int   g_idx[BB * TT];
__device__ int   g_fb_count;
__device__ int   g_fb_list[BB];

// ---------------------------------------------------------------------------
// helpers
// ---------------------------------------------------------------------------
__device__ __forceinline__ uint32_t smem_u32(const void* p) {
    uint32_t a;
    asm("{ .reg .u64 t; cvta.to.shared.u64 t, %1; cvt.u32.u64 %0, t; }" : "=r"(a) : "l"(p));
    return a;
}
__device__ __forceinline__ uint32_t lds_u32(uint32_t a) {
    uint32_t v; asm volatile("ld.shared.u32 %0, [%1];" : "=r"(v) : "r"(a)); return v;
}
__device__ __forceinline__ void sts_v4(uint32_t a, uint32_t x, uint32_t y, uint32_t z, uint32_t w) {
    asm volatile("st.shared.v4.u32 [%0], {%1,%2,%3,%4};" :: "r"(a), "r"(x), "r"(y), "r"(z), "r"(w) : "memory");
}
__device__ __forceinline__ void stg_cs(float4* p, float4 v) {
    asm volatile("st.global.cs.v4.f32 [%0], {%1,%2,%3,%4};"
                 :: "l"(p), "f"(v.x), "f"(v.y), "f"(v.z), "f"(v.w) : "memory");
}

// fp16 split of two adjacent fp32 values -> (hi half2, lo half2)
__device__ __forceinline__ void h2_split(float f0, float f1, uint32_t& hi, uint32_t& lo) {
    half2 h = __floats2half2_rn(f0, f1);
    float2 hf = __half22float2(h);
    half2 l = __floats2half2_rn(f0 - hf.x, f1 - hf.y);
    hi = *(uint32_t*)&h;
    lo = *(uint32_t*)&l;
}

__device__ __forceinline__ void mma_f16(float* d, const uint32_t* a, uint32_t b0, uint32_t b1) {
    asm volatile(
        "mma.sync.aligned.m16n8k16.row.col.f32.f16.f16.f32 "
        "{%0,%1,%2,%3}, {%4,%5,%6,%7}, {%8,%9}, {%0,%1,%2,%3};"
        : "+f"(d[0]), "+f"(d[1]), "+f"(d[2]), "+f"(d[3])
        : "r"(a[0]), "r"(a[1]), "r"(a[2]), "r"(a[3]), "r"(b0), "r"(b1));
}

// ---------------------------------------------------------------------------
// GEMM (R10 config — best measured): h = relu(x @ W1 + b1)
// ---------------------------------------------------------------------------
#define A_WORDS (128 * 36)
#define B_WORDS (16 * 264)
#define STAGE_WORDS (A_WORDS + B_WORDS)
#define GEMM_SMEM (2 * STAGE_WORDS * 4)

__global__ __launch_bounds__(256, 2)
void hmma_gemm(const float* __restrict__ A, const float* __restrict__ W,
               const float* __restrict__ bias, float* __restrict__ C,
               int K, int relu)
{
    extern __shared__ uint32_t sm[];
    const uint32_t sbase = smem_u32(sm);

    const int t   = threadIdx.x;
    const int wid = t >> 5;
    const int lid = t & 31;
    const int g   = lid >> 2;
    const int t4  = lid & 3;
    const int wm  = wid & 3;
    const int wn  = wid >> 2;

    const int m0 = blockIdx.y * 128;
    const int n0 = blockIdx.x * 128;

    const int aRow = t >> 1;
    const int aP8  = (t & 1) * 8;
    const float* Ag = A + (size_t)(m0 + aRow) * K + aP8 * 2;
    const int bP = t >> 4;
    const int bN = (t & 15) * 8;
    const float* Bg = W + (size_t)(2 * bP) * HH + n0 + bN;

    const uint32_t aSts = sbase + (uint32_t)(aRow * 36 + aP8) * 4u;
    const uint32_t bSts = sbase + (uint32_t)(A_WORDS + bP * 264 + bN) * 4u;

    float acc[2][8][4];
#pragma unroll
    for (int i = 0; i < 2; i++)
#pragma unroll
        for (int j = 0; j < 8; j++)
#pragma unroll
            for (int q = 0; q < 4; q++) acc[i][j][q] = 0.0f;

    const int NC = K / 32;

    float4 ra[4], rb0[2], rb1[2];
#pragma unroll
    for (int q = 0; q < 4; q++) ra[q] = *(const float4*)(Ag + 4 * q);
#pragma unroll
    for (int q = 0; q < 2; q++) {
        rb0[q] = *(const float4*)(Bg + 4 * q);
        rb1[q] = *(const float4*)(Bg + HH + 4 * q);
    }

    for (int c = 0; c < NC; c++) {
        const uint32_t soff = (uint32_t)((c & 1) * STAGE_WORDS) * 4u;

        {
            const float* af = (const float*)ra;
            uint32_t hi[8], lo[8];
#pragma unroll
            for (int j = 0; j < 8; j++)
                h2_split(af[2 * j], af[2 * j + 1], hi[j], lo[j]);
            sts_v4(aSts + soff,      hi[0], hi[1], hi[2], hi[3]);
            sts_v4(aSts + soff + 16, hi[4], hi[5], hi[6], hi[7]);
            sts_v4(aSts + soff + 64, lo[0], lo[1], lo[2], lo[3]);
            sts_v4(aSts + soff + 80, lo[4], lo[5], lo[6], lo[7]);

            const float* b0f = (const float*)rb0;
            const float* b1f = (const float*)rb1;
#pragma unroll
            for (int j = 0; j < 8; j++)
                h2_split(b0f[j], b1f[j], hi[j], lo[j]);
            sts_v4(bSts + soff,       hi[0], hi[1], hi[2], hi[3]);
            sts_v4(bSts + soff + 16,  hi[4], hi[5], hi[6], hi[7]);
            sts_v4(bSts + soff + 528, lo[0], lo[1], lo[2], lo[3]);
            sts_v4(bSts + soff + 544, lo[4], lo[5], lo[6], lo[7]);
        }
        __syncthreads();

        if (c + 1 < NC) {
            const float* ap = Ag + (size_t)(c + 1) * 32;
#pragma unroll
            for (int q = 0; q < 4; q++) ra[q] = *(const float4*)(ap + 4 * q);
            const float* bp = Bg + (size_t)(c + 1) * 32 * HH;
#pragma unroll
            for (int q = 0; q < 2; q++) {
                rb0[q] = *(const float4*)(bp + 4 * q);
                rb1[q] = *(const float4*)(bp + HH + 4 * q);
            }
        }

        const uint32_t sA = sbase + soff;
        const uint32_t sB = sbase + soff + A_WORDS * 4u;

#pragma unroll
        for (int ks = 0; ks < 2; ks++) {
            uint32_t Ahi[2][4], Alo[2][4];
#pragma unroll
            for (int mt = 0; mt < 2; mt++) {
                const uint32_t r0 = (uint32_t)(wm * 32 + mt * 16 + g) * 36u;
                const uint32_t r8 = r0 + 8u * 36u;
                const uint32_t p  = (uint32_t)(8 * ks + t4);
                Ahi[mt][0] = lds_u32(sA + (r0 + p) * 4u);
                Ahi[mt][1] = lds_u32(sA + (r8 + p) * 4u);
                Ahi[mt][2] = lds_u32(sA + (r0 + p + 4u) * 4u);
                Ahi[mt][3] = lds_u32(sA + (r8 + p + 4u) * 4u);
                Alo[mt][0] = lds_u32(sA + (r0 + p + 16u) * 4u);
                Alo[mt][1] = lds_u32(sA + (r8 + p + 16u) * 4u);
                Alo[mt][2] = lds_u32(sA + (r0 + p + 20u) * 4u);
                Alo[mt][3] = lds_u32(sA + (r8 + p + 20u) * 4u);
            }
            const uint32_t pr0 = (uint32_t)(8 * ks + t4) * 264u;
            const uint32_t pr1 = pr0 + 4u * 264u;
#pragma unroll
            for (int nt = 0; nt < 8; nt++) {
                const uint32_t n = (uint32_t)(wn * 64 + nt * 8 + g);
                uint32_t bh0 = lds_u32(sB + (pr0 + n) * 4u);
                uint32_t bh1 = lds_u32(sB + (pr1 + n) * 4u);
                uint32_t bl0 = lds_u32(sB + (pr0 + 132u + n) * 4u);
                uint32_t bl1 = lds_u32(sB + (pr1 + 132u + n) * 4u);
#pragma unroll
                for (int mt = 0; mt < 2; mt++) {
                    mma_f16(acc[mt][nt], Ahi[mt], bh0, bh1);
                    mma_f16(acc[mt][nt], Alo[mt], bh0, bh1);
                    mma_f16(acc[mt][nt], Ahi[mt], bl0, bl1);
                }
            }
        }
        __syncthreads();
    }

#pragma unroll
    for (int mt = 0; mt < 2; mt++) {
        int row = m0 + wm * 32 + mt * 16 + g;
#pragma unroll
        for (int nt = 0; nt < 8; nt++) {
            int col = n0 + wn * 64 + nt * 8 + 2 * t4;
            float2 bv = *(const float2*)(bias + col);
            float v0 = acc[mt][nt][0] + bv.x;
            float v1 = acc[mt][nt][1] + bv.y;
            float v2 = acc[mt][nt][2] + bv.x;
            float v3 = acc[mt][nt][3] + bv.y;
            if (relu) {
                v0 = fmaxf(v0, 0.f); v1 = fmaxf(v1, 0.f);
                v2 = fmaxf(v2, 0.f); v3 = fmaxf(v3, 0.f);
            }
            *(float2*)(C + (size_t)row * HH + col) = make_float2(v0, v1);
            *(float2*)(C + (size_t)(row + 8) * HH + col) = make_float2(v2, v3);
        }
    }
}

// ---------------------------------------------------------------------------
__global__ void reset_kernel() { g_fb_count = 0; }

// ---------------------------------------------------------------------------
// Wc = W2 @ Ws  [2048 x 48]
// ---------------------------------------------------------------------------
__global__ __launch_bounds__(256, 4)
void wc_kernel(const float* __restrict__ W2, const float* __restrict__ Ws)
{
    __shared__ float es[16][128];
    __shared__ float ws[128][48];

    int r0 = blockIdx.x * 16;
    int t  = threadIdx.x;
    int r  = t >> 4;
    int c  = t & 15;

    float a0 = 0.f, a1 = 0.f, a2 = 0.f;

    for (int k0 = 0; k0 < HH; k0 += 128) {
        for (int i = t; i < 512; i += 256) {
            int rr = i >> 5, cc = (i & 31) << 2;
            *(float4*)&es[rr][cc] =
                *(const float4*)(W2 + (size_t)(r0 + rr) * HH + k0 + cc);
        }
        for (int i = t; i < 1536; i += 256) {
            int rr = i / 12, cc = (i % 12) << 2;
            *(float4*)&ws[rr][cc] = *(const float4*)(Ws + (size_t)(k0 + rr) * 48 + cc);
        }
        __syncthreads();
        float p0 = 0.f, p1 = 0.f, p2 = 0.f;
#pragma unroll 4
        for (int k = 0; k < 128; k++) {
            float e = es[r][k];
            p0 = fmaf(e, ws[k][c],      p0);
            p1 = fmaf(e, ws[k][c + 16], p1);
            p2 = fmaf(e, ws[k][c + 32], p2);
        }
        a0 += p0; a1 += p1; a2 += p2;
        __syncthreads();
    }

    g_wc[(size_t)(r0 + r) * 48 + c]      = a0;
    g_wc[(size_t)(r0 + r) * 48 + c + 16] = a1;
    g_wc[(size_t)(r0 + r) * 48 + c + 32] = a2;
}

// bc = b2 @ Ws + bs : one block per output, tree reduction
__global__ __launch_bounds__(256, 4)
void bc_kernel(const float* __restrict__ b2, const float* __restrict__ Ws,
               const float* __restrict__ bs)
{
    __shared__ float red[256];
    int j = blockIdx.x;
    int t = threadIdx.x;
    float a = 0.f;
    for (int k = t; k < HH; k += 256)
        a = fmaf(b2[k], Ws[(size_t)k * 48 + j], a);
    red[t] = a;
    __syncthreads();
    for (int s = 128; s > 0; s >>= 1) {
        if (t < s) red[t] += red[t + s];
        __syncthreads();
    }
    if (t == 0) g_bc[j] = red[0] + bs[j];
}

// ---------------------------------------------------------------------------
// logits = g_h @ g_wc + g_bc ; argmax -> g_idx ; near-ties flagged
// ---------------------------------------------------------------------------
__global__ __launch_bounds__(256, 4)
void logits_argmax_kernel(float* __restrict__ out_logits, int write_logits)
{
    __shared__ float es[16][128];
    __shared__ float ws[128][48];
    __shared__ float ls[16][48];
    __shared__ int   sflag[16];

    int b0 = blockIdx.x * 16;
    int t  = threadIdx.x;
    int r  = t >> 4;
    int c  = t & 15;

    if (t < 16) sflag[t] = 0;

    float acc0 = 0.f, acc1 = 0.f, acc2 = 0.f;

    for (int k0 = 0; k0 < HH; k0 += 128) {
        for (int i = t; i < 512; i += 256) {
            int rr = i >> 5, cc = (i & 31) << 2;
            *(float4*)&es[rr][cc] =
                *(const float4*)(g_h + (size_t)(b0 + rr) * HH + k0 + cc);
        }
        for (int i = t; i < 1536; i += 256) {
            int rr = i / 12, cc = (i % 12) << 2;
            *(float4*)&ws[rr][cc] = *(const float4*)(g_wc + (size_t)(k0 + rr) * 48 + cc);
        }
        __syncthreads();
        float p0 = 0.f, p1 = 0.f, p2 = 0.f;
#pragma unroll 4
        for (int k = 0; k < 128; k++) {
            float e = es[r][k];
            p0 = fmaf(e, ws[k][c],      p0);
            p1 = fmaf(e, ws[k][c + 16], p1);
            p2 = fmaf(e, ws[k][c + 32], p2);
        }
        acc0 += p0; acc1 += p1; acc2 += p2;
        __syncthreads();
    }

    ls[r][c]      = acc0 + g_bc[c];
    ls[r][c + 16] = acc1 + g_bc[c + 16];
    ls[r][c + 32] = acc2 + g_bc[c + 32];
    __syncthreads();

    if (write_logits) {
        for (int i = t; i < 16 * 48; i += 256) {
            int rr = i / 48, cc = i % 48;
            out_logits[(size_t)(b0 + rr) * 48 + cc] = ls[rr][cc];
        }
    }
    if (t < 128) {
        int rr = t >> 3, tt = t & 7;
        const float* lp = &ls[rr][tt * 6];
        float best = lp[0], second = -3.4e38f;
        int bi = 0;
#pragma unroll
        for (int m = 1; m < 6; m++) {
            float v = lp[m];
            if (v > best) { second = best; best = v; bi = m; }
            else if (v > second) second = v;
        }
        g_idx[(b0 + rr) * TT + tt] = bi;
        if (best - second < GAP_THR) sflag[rr] = 1;
    }
    __syncthreads();
    if (t < 16 && sflag[t]) {
        int pos = atomicAdd(&g_fb_count, 1);
        g_fb_list[pos] = b0 + t;
    }
}

// ---------------------------------------------------------------------------
// Exact fp32 fallback for flagged samples (writes corrected g_idx)
// ---------------------------------------------------------------------------
__global__ __launch_bounds__(256, 1)
void fallback_kernel(const float* __restrict__ x,
                     const float* __restrict__ W1, const float* __restrict__ b1,
                     const float* __restrict__ W2, const float* __restrict__ b2,
                     const float* __restrict__ Ws, const float* __restrict__ bs)
{
    __shared__ float xs[1024];
    __shared__ float hs[2048];
    __shared__ float es2[2048];
    __shared__ float ls[48];

    const int t = threadIdx.x;
    const int total = g_fb_count;

    for (int idx = blockIdx.x; idx < total; idx += gridDim.x) {
        const int b = g_fb_list[idx];

        float ha[8];
#pragma unroll
        for (int m = 0; m < 8; m++) ha[m] = 0.f;
        for (int k0 = 0; k0 < DD; k0 += 1024) {
            __syncthreads();
            for (int i = t; i < 256; i += 256)
                *(float4*)&xs[i * 4] = *(const float4*)(x + (size_t)b * DD + k0 + i * 4);
            __syncthreads();
#pragma unroll 8
            for (int k = 0; k < 1024; k++) {
                float xv = xs[k];
                const float* wrow = W1 + (size_t)(k0 + k) * HH + t;
#pragma unroll
                for (int m = 0; m < 8; m++)
                    ha[m] = fmaf(xv, wrow[256 * m], ha[m]);
            }
        }
        __syncthreads();
#pragma unroll
        for (int m = 0; m < 8; m++)
            hs[t + 256 * m] = fmaxf(ha[m] + b1[t + 256 * m], 0.f);
        __syncthreads();

        float ea[8];
#pragma unroll
        for (int m = 0; m < 8; m++) ea[m] = 0.f;
#pragma unroll 8
        for (int k = 0; k < HH; k++) {
            float hv = hs[k];
            const float* wrow = W2 + (size_t)k * HH + t;
#pragma unroll
            for (int m = 0; m < 8; m++)
                ea[m] = fmaf(hv, wrow[256 * m], ea[m]);
        }
#pragma unroll
        for (int m = 0; m < 8; m++)
            es2[t + 256 * m] = ea[m] + b2[t + 256 * m];
        __syncthreads();

        if (t < 48) {
            float a = 0.f;
#pragma unroll 8
            for (int k = 0; k < HH; k++)
                a = fmaf(es2[k], Ws[(size_t)k * 48 + t], a);
            ls[t] = a + bs[t];
        }
        __syncthreads();
        if (t < 8) {
            const float* lp = &ls[t * 6];
            float best = lp[0]; int bi = 0;
#pragma unroll
            for (int m = 1; m < 6; m++) {
                float v = lp[m];
                if (v > best) { best = v; bi = m; }
            }
            g_idx[b * TT + t] = bi;
        }
        __syncthreads();
    }
}

// ---------------------------------------------------------------------------
// Bitonic sort of rows [b_off, b_off+grid) of x -> g_xs
// ---------------------------------------------------------------------------
__global__ __launch_bounds__(1024, 2)
void sort_rows_kernel(const float* __restrict__ x, int b_off)
{
    __shared__ float s[4096];
    int b = blockIdx.x + b_off;
    const float* xp = x + (size_t)b * DD;
    for (int i = threadIdx.x; i < 4096; i += 1024) s[i] = xp[i];
    __syncthreads();

    for (int k = 2; k <= 4096; k <<= 1) {
        for (int j = k >> 1; j > 0; j >>= 1) {
#pragma unroll
            for (int base = 0; base < 4096; base += 1024) {
                int i   = base + threadIdx.x;
                int ixj = i ^ j;
                if (ixj > i) {
                    bool asc = ((i & k) == 0);
                    float a = s[i], bb = s[ixj];
                    if ((a > bb) == asc) { s[i] = bb; s[ixj] = a; }
                }
            }
            __syncthreads();
        }
    }
    float* op = g_xs + (size_t)b * DD;
    for (int i = threadIdx.x; i < 4096; i += 1024) op[i] = s[i];
}

// ---------------------------------------------------------------------------
// Shared emit body: outputs[b,t,:] = a_t * perm_t(x_b) + c_t (512 threads)
// ---------------------------------------------------------------------------
__device__ __forceinline__ void emit_one(
    int b, const float* __restrict__ x,
    float ad, float su, float mu, float dv,
    float* __restrict__ out)
{
    __shared__ float sa[8], sb[8];
    __shared__ int   sm8[8];

    if (threadIdx.x == 0) {
        float A = 1.0f, Bc = 0.0f;
        int mode = 0;
#pragma unroll
        for (int t = 0; t < 8; t++) {
            int m = g_idx[b * 8 + t];
            switch (m) {
                case 0: mode = 2;              break;
                case 1: mode ^= 1;             break;
                case 2: Bc += ad;              break;
                case 3: Bc -= su;              break;
                case 4: A *= mu; Bc *= mu;     break;
                case 5: A /= dv; Bc /= dv;     break;
            }
            sa[t] = A; sb[t] = Bc; sm8[t] = mode;
        }
    }
    __syncthreads();

    const float4* xr  = (const float4*)(x    + (size_t)b * DD);
    const float4* xsr = (const float4*)(g_xs + (size_t)b * DD);
    float* ob = out + (size_t)b * ((size_t)TT * DD);
    const int Q = DD / 4;

#pragma unroll 1
    for (int t = 0; t < 8; t++) {
        float A = sa[t], Bc = sb[t];
        int mode = sm8[t];
        const float4* src = (mode & 2) ? xsr : xr;
        bool rev = (mode & 1);
        float4* op = (float4*)(ob + (size_t)t * DD);
#pragma unroll
        for (int u = 0; u < 2; u++) {
            int i = threadIdx.x + 512 * u;
            float4 v;
            if (!rev) {
                v = src[i];
            } else {
                float4 w = src[Q - 1 - i];
                v.x = w.w; v.y = w.z; v.z = w.y; v.w = w.x;
            }
            v.x = fmaf(A, v.x, Bc);
            v.y = fmaf(A, v.y, Bc);
            v.z = fmaf(A, v.z, Bc);
            v.w = fmaf(A, v.w, Bc);
            stg_cs(&op[i], v);
        }
    }
    __syncthreads();
}

__global__ __launch_bounds__(512, 4)
void emit_kernel(const float* __restrict__ x,
                 const float* __restrict__ add_s, const float* __restrict__ sub_s,
                 const float* __restrict__ mul_s, const float* __restrict__ div_s,
                 float* __restrict__ out)
{
    emit_one(blockIdx.x, x, *add_s, *sub_s, *mul_s, *div_s + 1e-5f, out);
}

// re-emit flagged samples with corrected g_idx (after fallback join)
__global__ __launch_bounds__(512, 4)
void re_emit_kernel(const float* __restrict__ x,
                    const float* __restrict__ add_s, const float* __restrict__ sub_s,
                    const float* __restrict__ mul_s, const float* __restrict__ div_s,
                    float* __restrict__ out)
{
    const int total = g_fb_count;
    for (int idx = blockIdx.x; idx < total; idx += gridDim.x)
        emit_one(g_fb_list[idx], x, *add_s, *sub_s, *mul_s, *div_s + 1e-5f, out);
}

// ---------------------------------------------------------------------------
extern "C" void kernel_launch(void* const* d_in, const int* in_sizes, int n_in,
                              void* d_out, int out_size)
{
    const float* x     = (const float*)d_in[0];
    const float* W1    = (const float*)d_in[1];
    const float* b1    = (const float*)d_in[2];
    const float* W2    = (const float*)d_in[3];
    const float* b2    = (const float*)d_in[4];
    const float* Ws    = (const float*)d_in[5];
    const float* bs    = (const float*)d_in[6];
    const float* add_s = (const float*)d_in[7];
    const float* sub_s = (const float*)d_in[8];
    const float* mul_s = (const float*)d_in[9];
    const float* div_s = (const float*)d_in[10];
    float* out = (float*)d_out;

    const size_t out_main = (size_t)BB * TT * DD;
    const size_t out_need = out_main + (size_t)BB * TT * MM;
    int write_logits = ((size_t)out_size >= out_need) ? 1 : 0;
    float* out_logits = out + out_main;

    static cudaStream_t s_aux = nullptr;
    static cudaEvent_t ev_fork = nullptr, ev_aux1 = nullptr, ev_logits = nullptr, ev_fb = nullptr;
    if (s_aux == nullptr) {
        cudaStreamCreateWithFlags(&s_aux, cudaStreamNonBlocking);
        cudaEventCreateWithFlags(&ev_fork,   cudaEventDisableTiming);
        cudaEventCreateWithFlags(&ev_aux1,   cudaEventDisableTiming);
        cudaEventCreateWithFlags(&ev_logits, cudaEventDisableTiming);
        cudaEventCreateWithFlags(&ev_fb,     cudaEventDisableTiming);
        cudaFuncSetAttribute(hmma_gemm, cudaFuncAttributeMaxDynamicSharedMemorySize, GEMM_SMEM);
    }

    float* d_gh;  cudaGetSymbolAddress((void**)&d_gh,  g_h);

    // main: reset -> fork
    reset_kernel<<<1, 1>>>();
    cudaEventRecord(ev_fork, 0);
    cudaStreamWaitEvent(s_aux, ev_fork, 0);

    // aux: sorts + wc + bc (concurrent with gemm1)
    sort_rows_kernel<<<BB / 2, 1024, 0, s_aux>>>(x, 0);
    sort_rows_kernel<<<BB / 2, 1024, 0, s_aux>>>(x, BB / 2);
    wc_kernel<<<HH / 16, 256, 0, s_aux>>>(W2, Ws);
    bc_kernel<<<48, 256, 0, s_aux>>>(b2, Ws, bs);
    cudaEventRecord(ev_aux1, s_aux);

    // main: gemm1
    dim3 g(HH / 128, BB / 128);
    hmma_gemm<<<g, 256, GEMM_SMEM>>>(x, W1, b1, d_gh, DD, 1);

    // main waits for aux prep, then logits
    cudaStreamWaitEvent(0, ev_aux1, 0);
    logits_argmax_kernel<<<BB / 16, 256>>>(out_logits, write_logits);
    cudaEventRecord(ev_logits, 0);

    // aux: fallback (needs logits) runs concurrently with emit on main
    cudaStreamWaitEvent(s_aux, ev_logits, 0);
    fallback_kernel<<<128, 256, 0, s_aux>>>(x, W1, b1, W2, b2, Ws, bs);
    cudaEventRecord(ev_fb, s_aux);

    // main: emit all samples (flagged ones fixed below)
    emit_kernel<<<BB, 512>>>(x, add_s, sub_s, mul_s, div_s, out);

    // join: re-emit flagged samples with corrected routing
    cudaStreamWaitEvent(0, ev_fb, 0);
    re_emit_kernel<<<64, 512>>>(x, add_s, sub_s, mul_s, div_s, out);
}

// round 15
// speedup vs baseline: 1.0811x; 1.0811x over previous
#include <cuda_runtime.h>
#include <cuda_fp16.h>
#include <cstdint>
#include <cstddef>

// Problem constants
#define BB 4096
#define DD 4096
#define HH 2048
#define TT 8
#define MM 6

#define GAP_THR 5e-4f
#define FB_SLOTS 4096

// Scratch (device globals)
__device__ float g_h[(size_t)BB * HH];
__device__ float g_xs[(size_t)BB * DD];
__device__ float g_wc[(size_t)HH * 48];   // W2 @ Ws
__device__ float g_bc[48];                // b2 @ Ws + bs
__device__ float g_hf[(size_t)FB_SLOTS * HH];  // exact h (flagged)
__device__ float g_ef[(size_t)FB_SLOTS * HH];  // exact enc (flagged)
__device__ int   g_idx[BB * TT];
__device__ int   g_fb_count;
__device__ int   g_fb_list[BB];

// ---------------------------------------------------------------------------
// helpers
// ---------------------------------------------------------------------------
__device__ __forceinline__ uint32_t smem_u32(const void* p) {
    uint32_t a;
    asm("{ .reg .u64 t; cvta.to.shared.u64 t, %1; cvt.u32.u64 %0, t; }" : "=r"(a) : "l"(p));
    return a;
}
__device__ __forceinline__ uint32_t lds_u32(uint32_t a) {
    uint32_t v; asm volatile("ld.shared.u32 %0, [%1];" : "=r"(v) : "r"(a)); return v;
}
__device__ __forceinline__ void sts_v4(uint32_t a, uint32_t x, uint32_t y, uint32_t z, uint32_t w) {
    asm volatile("st.shared.v4.u32 [%0], {%1,%2,%3,%4};" :: "r"(a), "r"(x), "r"(y), "r"(z), "r"(w) : "memory");
}
__device__ __forceinline__ void stg_cs(float4* p, float4 v) {
    asm volatile("st.global.cs.v4.f32 [%0], {%1,%2,%3,%4};"
                 :: "l"(p), "f"(v.x), "f"(v.y), "f"(v.z), "f"(v.w) : "memory");
}

// fp16 split of two adjacent fp32 values -> (hi half2, lo half2)
__device__ __forceinline__ void h2_split(float f0, float f1, uint32_t& hi, uint32_t& lo) {
    half2 h = __floats2half2_rn(f0, f1);
    float2 hf = __half22float2(h);
    half2 l = __floats2half2_rn(f0 - hf.x, f1 - hf.y);
    hi = *(uint32_t*)&h;
    lo = *(uint32_t*)&l;
}

__device__ __forceinline__ void mma_f16(float* d, const uint32_t* a, uint32_t b0, uint32_t b1) {
    asm volatile(
        "mma.sync.aligned.m16n8k16.row.col.f32.f16.f16.f32 "
        "{%0,%1,%2,%3}, {%4,%5,%6,%7}, {%8,%9}, {%0,%1,%2,%3};"
        : "+f"(d[0]), "+f"(d[1]), "+f"(d[2]), "+f"(d[3])
        : "r"(a[0]), "r"(a[1]), "r"(a[2]), "r"(a[3]), "r"(b0), "r"(b1));
}

// ---------------------------------------------------------------------------
// GEMM (R10 config — best measured): h = relu(x @ W1 + b1)
// ---------------------------------------------------------------------------
#define A_WORDS (128 * 36)
#define B_WORDS (16 * 264)
#define STAGE_WORDS (A_WORDS + B_WORDS)
#define GEMM_SMEM (2 * STAGE_WORDS * 4)

__global__ __launch_bounds__(256, 2)
void hmma_gemm(const float* __restrict__ A, const float* __restrict__ W,
               const float* __restrict__ bias, float* __restrict__ C,
               int K, int relu)
{
    extern __shared__ uint32_t sm[];
    const uint32_t sbase = smem_u32(sm);

    const int t   = threadIdx.x;
    const int wid = t >> 5;
    const int lid = t & 31;
    const int g   = lid >> 2;
    const int t4  = lid & 3;
    const int wm  = wid & 3;
    const int wn  = wid >> 2;

    const int m0 = blockIdx.y * 128;
    const int n0 = blockIdx.x * 128;

    const int aRow = t >> 1;
    const int aP8  = (t & 1) * 8;
    const float* Ag = A + (size_t)(m0 + aRow) * K + aP8 * 2;
    const int bP = t >> 4;
    const int bN = (t & 15) * 8;
    const float* Bg = W + (size_t)(2 * bP) * HH + n0 + bN;

    const uint32_t aSts = sbase + (uint32_t)(aRow * 36 + aP8) * 4u;
    const uint32_t bSts = sbase + (uint32_t)(A_WORDS + bP * 264 + bN) * 4u;

    float acc[2][8][4];
#pragma unroll
    for (int i = 0; i < 2; i++)
#pragma unroll
        for (int j = 0; j < 8; j++)
#pragma unroll
            for (int q = 0; q < 4; q++) acc[i][j][q] = 0.0f;

    const int NC = K / 32;

    float4 ra[4], rb0[2], rb1[2];
#pragma unroll
    for (int q = 0; q < 4; q++) ra[q] = *(const float4*)(Ag + 4 * q);
#pragma unroll
    for (int q = 0; q < 2; q++) {
        rb0[q] = *(const float4*)(Bg + 4 * q);
        rb1[q] = *(const float4*)(Bg + HH + 4 * q);
    }

    for (int c = 0; c < NC; c++) {
        const uint32_t soff = (uint32_t)((c & 1) * STAGE_WORDS) * 4u;

        {
            const float* af = (const float*)ra;
            uint32_t hi[8], lo[8];
#pragma unroll
            for (int j = 0; j < 8; j++)
                h2_split(af[2 * j], af[2 * j + 1], hi[j], lo[j]);
            sts_v4(aSts + soff,      hi[0], hi[1], hi[2], hi[3]);
            sts_v4(aSts + soff + 16, hi[4], hi[5], hi[6], hi[7]);
            sts_v4(aSts + soff + 64, lo[0], lo[1], lo[2], lo[3]);
            sts_v4(aSts + soff + 80, lo[4], lo[5], lo[6], lo[7]);

            const float* b0f = (const float*)rb0;
            const float* b1f = (const float*)rb1;
#pragma unroll
            for (int j = 0; j < 8; j++)
                h2_split(b0f[j], b1f[j], hi[j], lo[j]);
            sts_v4(bSts + soff,       hi[0], hi[1], hi[2], hi[3]);
            sts_v4(bSts + soff + 16,  hi[4], hi[5], hi[6], hi[7]);
            sts_v4(bSts + soff + 528, lo[0], lo[1], lo[2], lo[3]);
            sts_v4(bSts + soff + 544, lo[4], lo[5], lo[6], lo[7]);
        }
        __syncthreads();

        if (c + 1 < NC) {
            const float* ap = Ag + (size_t)(c + 1) * 32;
#pragma unroll
            for (int q = 0; q < 4; q++) ra[q] = *(const float4*)(ap + 4 * q);
            const float* bp = Bg + (size_t)(c + 1) * 32 * HH;
#pragma unroll
            for (int q = 0; q < 2; q++) {
                rb0[q] = *(const float4*)(bp + 4 * q);
                rb1[q] = *(const float4*)(bp + HH + 4 * q);
            }
        }

        const uint32_t sA = sbase + soff;
        const uint32_t sB = sbase + soff + A_WORDS * 4u;

#pragma unroll
        for (int ks = 0; ks < 2; ks++) {
            uint32_t Ahi[2][4], Alo[2][4];
#pragma unroll
            for (int mt = 0; mt < 2; mt++) {
                const uint32_t r0 = (uint32_t)(wm * 32 + mt * 16 + g) * 36u;
                const uint32_t r8 = r0 + 8u * 36u;
                const uint32_t p  = (uint32_t)(8 * ks + t4);
                Ahi[mt][0] = lds_u32(sA + (r0 + p) * 4u);
                Ahi[mt][1] = lds_u32(sA + (r8 + p) * 4u);
                Ahi[mt][2] = lds_u32(sA + (r0 + p + 4u) * 4u);
                Ahi[mt][3] = lds_u32(sA + (r8 + p + 4u) * 4u);
                Alo[mt][0] = lds_u32(sA + (r0 + p + 16u) * 4u);
                Alo[mt][1] = lds_u32(sA + (r8 + p + 16u) * 4u);
                Alo[mt][2] = lds_u32(sA + (r0 + p + 20u) * 4u);
                Alo[mt][3] = lds_u32(sA + (r8 + p + 20u) * 4u);
            }
            const uint32_t pr0 = (uint32_t)(8 * ks + t4) * 264u;
            const uint32_t pr1 = pr0 + 4u * 264u;
#pragma unroll
            for (int nt = 0; nt < 8; nt++) {
                const uint32_t n = (uint32_t)(wn * 64 + nt * 8 + g);
                uint32_t bh0 = lds_u32(sB + (pr0 + n) * 4u);
                uint32_t bh1 = lds_u32(sB + (pr1 + n) * 4u);
                uint32_t bl0 = lds_u32(sB + (pr0 + 132u + n) * 4u);
                uint32_t bl1 = lds_u32(sB + (pr1 + 132u + n) * 4u);
#pragma unroll
                for (int mt = 0; mt < 2; mt++) {
                    mma_f16(acc[mt][nt], Ahi[mt], bh0, bh1);
                    mma_f16(acc[mt][nt], Alo[mt], bh0, bh1);
                    mma_f16(acc[mt][nt], Ahi[mt], bl0, bl1);
                }
            }
        }
        __syncthreads();
    }

#pragma unroll
    for (int mt = 0; mt < 2; mt++) {
        int row = m0 + wm * 32 + mt * 16 + g;
#pragma unroll
        for (int nt = 0; nt < 8; nt++) {
            int col = n0 + wn * 64 + nt * 8 + 2 * t4;
            float2 bv = *(const float2*)(bias + col);
            float v0 = acc[mt][nt][0] + bv.x;
            float v1 = acc[mt][nt][1] + bv.y;
            float v2 = acc[mt][nt][2] + bv.x;
            float v3 = acc[mt][nt][3] + bv.y;
            if (relu) {
                v0 = fmaxf(v0, 0.f); v1 = fmaxf(v1, 0.f);
                v2 = fmaxf(v2, 0.f); v3 = fmaxf(v3, 0.f);
            }
            *(float2*)(C + (size_t)row * HH + col) = make_float2(v0, v1);
            *(float2*)(C + (size_t)(row + 8) * HH + col) = make_float2(v2, v3);
        }
    }
}

// ---------------------------------------------------------------------------
__global__ void reset_kernel() { g_fb_count = 0; }

// ---------------------------------------------------------------------------
// Wc = W2 @ Ws  [2048 x 48]
// ---------------------------------------------------------------------------
__global__ __launch_bounds__(256, 4)
void wc_kernel(const float* __restrict__ W2, const float* __restrict__ Ws)
{
    __shared__ float es[16][128];
    __shared__ float ws[128][48];

    int r0 = blockIdx.x * 16;
    int t  = threadIdx.x;
    int r  = t >> 4;
    int c  = t & 15;

    float a0 = 0.f, a1 = 0.f, a2 = 0.f;

    for (int k0 = 0; k0 < HH; k0 += 128) {
        for (int i = t; i < 512; i += 256) {
            int rr = i >> 5, cc = (i & 31) << 2;
            *(float4*)&es[rr][cc] =
                *(const float4*)(W2 + (size_t)(r0 + rr) * HH + k0 + cc);
        }
        for (int i = t; i < 1536; i += 256) {
            int rr = i / 12, cc = (i % 12) << 2;
            *(float4*)&ws[rr][cc] = *(const float4*)(Ws + (size_t)(k0 + rr) * 48 + cc);
        }
        __syncthreads();
        float p0 = 0.f, p1 = 0.f, p2 = 0.f;
#pragma unroll 4
        for (int k = 0; k < 128; k++) {
            float e = es[r][k];
            p0 = fmaf(e, ws[k][c],      p0);
            p1 = fmaf(e, ws[k][c + 16], p1);
            p2 = fmaf(e, ws[k][c + 32], p2);
        }
        a0 += p0; a1 += p1; a2 += p2;
        __syncthreads();
    }

    g_wc[(size_t)(r0 + r) * 48 + c]      = a0;
    g_wc[(size_t)(r0 + r) * 48 + c + 16] = a1;
    g_wc[(size_t)(r0 + r) * 48 + c + 32] = a2;
}

// bc = b2 @ Ws + bs
__global__ __launch_bounds__(256, 4)
void bc_kernel(const float* __restrict__ b2, const float* __restrict__ Ws,
               const float* __restrict__ bs)
{
    __shared__ float red[256];
    int j = blockIdx.x;
    int t = threadIdx.x;
    float a = 0.f;
    for (int k = t; k < HH; k += 256)
        a = fmaf(b2[k], Ws[(size_t)k * 48 + j], a);
    red[t] = a;
    __syncthreads();
    for (int s = 128; s > 0; s >>= 1) {
        if (t < s) red[t] += red[t + s];
        __syncthreads();
    }
    if (t == 0) g_bc[j] = red[0] + bs[j];
}

// ---------------------------------------------------------------------------
// logits = g_h @ g_wc + g_bc ; argmax -> g_idx ; near-ties flagged
// ---------------------------------------------------------------------------
__global__ __launch_bounds__(256, 4)
void logits_argmax_kernel(float* __restrict__ out_logits, int write_logits)
{
    __shared__ float es[16][128];
    __shared__ float ws[128][48];
    __shared__ float ls[16][48];
    __shared__ int   sflag[16];

    int b0 = blockIdx.x * 16;
    int t  = threadIdx.x;
    int r  = t >> 4;
    int c  = t & 15;

    if (t < 16) sflag[t] = 0;

    float acc0 = 0.f, acc1 = 0.f, acc2 = 0.f;

    for (int k0 = 0; k0 < HH; k0 += 128) {
        for (int i = t; i < 512; i += 256) {
            int rr = i >> 5, cc = (i & 31) << 2;
            *(float4*)&es[rr][cc] =
                *(const float4*)(g_h + (size_t)(b0 + rr) * HH + k0 + cc);
        }
        for (int i = t; i < 1536; i += 256) {
            int rr = i / 12, cc = (i % 12) << 2;
            *(float4*)&ws[rr][cc] = *(const float4*)(g_wc + (size_t)(k0 + rr) * 48 + cc);
        }
        __syncthreads();
        float p0 = 0.f, p1 = 0.f, p2 = 0.f;
#pragma unroll 4
        for (int k = 0; k < 128; k++) {
            float e = es[r][k];
            p0 = fmaf(e, ws[k][c],      p0);
            p1 = fmaf(e, ws[k][c + 16], p1);
            p2 = fmaf(e, ws[k][c + 32], p2);
        }
        acc0 += p0; acc1 += p1; acc2 += p2;
        __syncthreads();
    }

    ls[r][c]      = acc0 + g_bc[c];
    ls[r][c + 16] = acc1 + g_bc[c + 16];
    ls[r][c + 32] = acc2 + g_bc[c + 32];
    __syncthreads();

    if (write_logits) {
        for (int i = t; i < 16 * 48; i += 256) {
            int rr = i / 48, cc = i % 48;
            out_logits[(size_t)(b0 + rr) * 48 + cc] = ls[rr][cc];
        }
    }
    if (t < 128) {
        int rr = t >> 3, tt = t & 7;
        const float* lp = &ls[rr][tt * 6];
        float best = lp[0], second = -3.4e38f;
        int bi = 0;
#pragma unroll
        for (int m = 1; m < 6; m++) {
            float v = lp[m];
            if (v > best) { second = best; best = v; bi = m; }
            else if (v > second) second = v;
        }
        g_idx[(b0 + rr) * TT + tt] = bi;
        if (best - second < GAP_THR) sflag[rr] = 1;
    }
    __syncthreads();
    if (t < 16 && sflag[t]) {
        int pos = atomicAdd(&g_fb_count, 1);
        g_fb_list[pos] = b0 + t;
    }
}

// ---------------------------------------------------------------------------
// Parallel exact fp32 fallback (3 phases, column-parallel):
//   A: g_hf[s] = relu(x[b] @ W1 + b1)
//   B: g_ef[s] = g_hf[s] @ W2 + b2
//   C: logits = g_ef[s] @ Ws + bs ; argmax -> g_idx[b]
// ---------------------------------------------------------------------------
__global__ __launch_bounds__(256, 2)
void fb_h_kernel(const float* __restrict__ x,
                 const float* __restrict__ W1, const float* __restrict__ b1)
{
    __shared__ float xs[DD];
    const int total = g_fb_count;
    const int col = blockIdx.x * 256 + threadIdx.x;
    for (int s = blockIdx.y; s < total; s += gridDim.y) {
        const int b = g_fb_list[s];
        for (int i = threadIdx.x; i < DD / 4; i += 256)
            ((float4*)xs)[i] = ((const float4*)(x + (size_t)b * DD))[i];
        __syncthreads();
        float acc = 0.f;
#pragma unroll 4
        for (int k = 0; k < DD; k++)
            acc = fmaf(xs[k], W1[(size_t)k * HH + col], acc);
        g_hf[(size_t)s * HH + col] = fmaxf(acc + b1[col], 0.f);
        __syncthreads();
    }
}

__global__ __launch_bounds__(256, 2)
void fb_e_kernel(const float* __restrict__ W2, const float* __restrict__ b2)
{
    __shared__ float hs[HH];
    const int total = g_fb_count;
    const int col = blockIdx.x * 256 + threadIdx.x;
    for (int s = blockIdx.y; s < total; s += gridDim.y) {
        for (int i = threadIdx.x; i < HH / 4; i += 256)
            ((float4*)hs)[i] = ((const float4*)(g_hf + (size_t)s * HH))[i];
        __syncthreads();
        float acc = 0.f;
#pragma unroll 4
        for (int k = 0; k < HH; k++)
            acc = fmaf(hs[k], W2[(size_t)k * HH + col], acc);
        g_ef[(size_t)s * HH + col] = acc + b2[col];
        __syncthreads();
    }
}

__global__ __launch_bounds__(64, 8)
void fb_l_kernel(const float* __restrict__ Ws, const float* __restrict__ bs)
{
    __shared__ float ls[48];
    const int total = g_fb_count;
    const int t = threadIdx.x;
    for (int s = blockIdx.x; s < total; s += gridDim.x) {
        const int b = g_fb_list[s];
        if (t < 48) {
            float a = 0.f;
            const float* ep = g_ef + (size_t)s * HH;
            for (int k = 0; k < HH; k++)
                a = fmaf(ep[k], Ws[(size_t)k * 48 + t], a);
            ls[t] = a + bs[t];
        }
        __syncthreads();
        if (t < 8) {
            const float* lp = &ls[t * 6];
            float best = lp[0]; int bi = 0;
#pragma unroll
            for (int m = 1; m < 6; m++) {
                float v = lp[m];
                if (v > best) { best = v; bi = m; }
            }
            g_idx[b * TT + t] = bi;
        }
        __syncthreads();
    }
}

// ---------------------------------------------------------------------------
// Bitonic sort of rows [b_off, b_off+grid) of x -> g_xs
// ---------------------------------------------------------------------------
__global__ __launch_bounds__(1024, 2)
void sort_rows_kernel(const float* __restrict__ x, int b_off)
{
    __shared__ float s[4096];
    int b = blockIdx.x + b_off;
    const float* xp = x + (size_t)b * DD;
    for (int i = threadIdx.x; i < 4096; i += 1024) s[i] = xp[i];
    __syncthreads();

    for (int k = 2; k <= 4096; k <<= 1) {
        for (int j = k >> 1; j > 0; j >>= 1) {
#pragma unroll
            for (int base = 0; base < 4096; base += 1024) {
                int i   = base + threadIdx.x;
                int ixj = i ^ j;
                if (ixj > i) {
                    bool asc = ((i & k) == 0);
                    float a = s[i], bb = s[ixj];
                    if ((a > bb) == asc) { s[i] = bb; s[ixj] = a; }
                }
            }
            __syncthreads();
        }
    }
    float* op = g_xs + (size_t)b * DD;
    for (int i = threadIdx.x; i < 4096; i += 1024) op[i] = s[i];
}

// ---------------------------------------------------------------------------
// Collapsed scan + emit: outputs[b,t,:] = a_t * perm_t(x_b) + c_t
// ---------------------------------------------------------------------------
__global__ __launch_bounds__(512, 4)
void emit_kernel(const float* __restrict__ x,
                 const float* __restrict__ add_s, const float* __restrict__ sub_s,
                 const float* __restrict__ mul_s, const float* __restrict__ div_s,
                 float* __restrict__ out)
{
    __shared__ float sa[8], sb[8];
    __shared__ int   sm8[8];
    int b = blockIdx.x;

    if (threadIdx.x == 0) {
        float A = 1.0f, Bc = 0.0f;
        int mode = 0;
        float ad = *add_s, su = *sub_s, mu = *mul_s;
        float dv = *div_s + 1e-5f;
#pragma unroll
        for (int t = 0; t < 8; t++) {
            int m = g_idx[b * 8 + t];
            switch (m) {
                case 0: mode = 2;              break;
                case 1: mode ^= 1;             break;
                case 2: Bc += ad;              break;
                case 3: Bc -= su;              break;
                case 4: A *= mu; Bc *= mu;     break;
                case 5: A /= dv; Bc /= dv;     break;
            }
            sa[t] = A; sb[t] = Bc; sm8[t] = mode;
        }
    }
    __syncthreads();

    const float4* xr  = (const float4*)(x    + (size_t)b * DD);
    const float4* xsr = (const float4*)(g_xs + (size_t)b * DD);
    float* ob = out + (size_t)b * ((size_t)TT * DD);
    const int Q = DD / 4;

#pragma unroll 1
    for (int t = 0; t < 8; t++) {
        float A = sa[t], Bc = sb[t];
        int mode = sm8[t];
        const float4* src = (mode & 2) ? xsr : xr;
        bool rev = (mode & 1);
        float4* op = (float4*)(ob + (size_t)t * DD);
#pragma unroll
        for (int u = 0; u < 2; u++) {
            int i = threadIdx.x + 512 * u;
            float4 v;
            if (!rev) {
                v = src[i];
            } else {
                float4 w = src[Q - 1 - i];
                v.x = w.w; v.y = w.z; v.z = w.y; v.w = w.x;
            }
            v.x = fmaf(A, v.x, Bc);
            v.y = fmaf(A, v.y, Bc);
            v.z = fmaf(A, v.z, Bc);
            v.w = fmaf(A, v.w, Bc);
            stg_cs(&op[i], v);
        }
    }
}

// ---------------------------------------------------------------------------
extern "C" void kernel_launch(void* const* d_in, const int* in_sizes, int n_in,
                              void* d_out, int out_size)
{
    const float* x     = (const float*)d_in[0];
    const float* W1    = (const float*)d_in[1];
    const float* b1    = (const float*)d_in[2];
    const float* W2    = (const float*)d_in[3];
    const float* b2    = (const float*)d_in[4];
    const float* Ws    = (const float*)d_in[5];
    const float* bs    = (const float*)d_in[6];
    const float* add_s = (const float*)d_in[7];
    const float* sub_s = (const float*)d_in[8];
    const float* mul_s = (const float*)d_in[9];
    const float* div_s = (const float*)d_in[10];
    float* out = (float*)d_out;

    const size_t out_main = (size_t)BB * TT * DD;
    const size_t out_need = out_main + (size_t)BB * TT * MM;
    int write_logits = ((size_t)out_size >= out_need) ? 1 : 0;
    float* out_logits = out + out_main;

    static cudaStream_t s_aux = nullptr;
    static cudaEvent_t ev_fork = nullptr, ev_aux1 = nullptr;
    if (s_aux == nullptr) {
        cudaStreamCreateWithFlags(&s_aux, cudaStreamNonBlocking);
        cudaEventCreateWithFlags(&ev_fork, cudaEventDisableTiming);
        cudaEventCreateWithFlags(&ev_aux1, cudaEventDisableTiming);
        cudaFuncSetAttribute(hmma_gemm, cudaFuncAttributeMaxDynamicSharedMemorySize, GEMM_SMEM);
    }

    float* d_gh;  cudaGetSymbolAddress((void**)&d_gh,  g_h);

    // main: reset -> fork
    reset_kernel<<<1, 1>>>();
    cudaEventRecord(ev_fork, 0);
    cudaStreamWaitEvent(s_aux, ev_fork, 0);

    // aux: sorts + wc + bc (concurrent with gemm1)
    sort_rows_kernel<<<BB / 2, 1024, 0, s_aux>>>(x, 0);
    sort_rows_kernel<<<BB / 2, 1024, 0, s_aux>>>(x, BB / 2);
    wc_kernel<<<HH / 16, 256, 0, s_aux>>>(W2, Ws);
    bc_kernel<<<48, 256, 0, s_aux>>>(b2, Ws, bs);
    cudaEventRecord(ev_aux1, s_aux);

    // main: gemm1
    dim3 g(HH / 128, BB / 128);
    hmma_gemm<<<g, 256, GEMM_SMEM>>>(x, W1, b1, d_gh, DD, 1);

    // main waits for aux prep, then logits
    cudaStreamWaitEvent(0, ev_aux1, 0);
    logits_argmax_kernel<<<BB / 16, 256>>>(out_logits, write_logits);

    // parallel exact fp32 fallback (column-parallel, L2-resident weights)
    fb_h_kernel<<<dim3(HH / 256, 64), 256>>>(x, W1, b1);
    fb_e_kernel<<<dim3(HH / 256, 64), 256>>>(W2, b2);
    fb_l_kernel<<<64, 64>>>(Ws, bs);

    // emit with final routing
    emit_kernel<<<BB, 512>>>(x, add_s, sub_s, mul_s, div_s, out);
}

// round 16
// speedup vs baseline: 1.3619x; 1.2597x over previous
#include <cuda_runtime.h>
#include <cuda_fp16.h>
#include <cstdint>
#include <cstddef>

// Problem constants
#define BB 4096
#define DD 4096
#define HH 2048
#define TT 8
#define MM 6

#define GAP_THR 5e-4f
#define FBM 256                  // max flagged samples handled

// Scratch (device globals)
__device__ float g_h[(size_t)BB * HH];
__device__ float g_xs[(size_t)BB * DD];
__device__ float g_wc[(size_t)HH * 48];
__device__ float g_bc[48];
__device__ float g_xf[(size_t)FBM * DD];   // gathered flagged x rows
__device__ float g_hf[(size_t)FBM * HH];   // exact h (flagged)
__device__ float g_ef[(size_t)FBM * HH];   // exact enc (flagged)
__device__ int   g_idx[BB * TT];
__device__ int   g_fb_count;
__device__ int   g_fb_list[BB];

// ---------------------------------------------------------------------------
// helpers
// ---------------------------------------------------------------------------
__device__ __forceinline__ uint32_t smem_u32(const void* p) {
    uint32_t a;
    asm("{ .reg .u64 t; cvta.to.shared.u64 t, %1; cvt.u32.u64 %0, t; }" : "=r"(a) : "l"(p));
    return a;
}
__device__ __forceinline__ uint32_t lds_u32(uint32_t a) {
    uint32_t v; asm volatile("ld.shared.u32 %0, [%1];" : "=r"(v) : "r"(a)); return v;
}
__device__ __forceinline__ void sts_v4(uint32_t a, uint32_t x, uint32_t y, uint32_t z, uint32_t w) {
    asm volatile("st.shared.v4.u32 [%0], {%1,%2,%3,%4};" :: "r"(a), "r"(x), "r"(y), "r"(z), "r"(w) : "memory");
}
__device__ __forceinline__ void stg_cs(float4* p, float4 v) {
    asm volatile("st.global.cs.v4.f32 [%0], {%1,%2,%3,%4};"
                 :: "l"(p), "f"(v.x), "f"(v.y), "f"(v.z), "f"(v.w) : "memory");
}

// fp16 split of two adjacent fp32 values -> (hi half2, lo half2)
__device__ __forceinline__ void h2_split(float f0, float f1, uint32_t& hi, uint32_t& lo) {
    half2 h = __floats2half2_rn(f0, f1);
    float2 hf = __half22float2(h);
    half2 l = __floats2half2_rn(f0 - hf.x, f1 - hf.y);
    hi = *(uint32_t*)&h;
    lo = *(uint32_t*)&l;
}

__device__ __forceinline__ void mma_f16(float* d, const uint32_t* a, uint32_t b0, uint32_t b1) {
    asm volatile(
        "mma.sync.aligned.m16n8k16.row.col.f32.f16.f16.f32 "
        "{%0,%1,%2,%3}, {%4,%5,%6,%7}, {%8,%9}, {%0,%1,%2,%3};"
        : "+f"(d[0]), "+f"(d[1]), "+f"(d[2]), "+f"(d[3])
        : "r"(a[0]), "r"(a[1]), "r"(a[2]), "r"(a[3]), "r"(b0), "r"(b1));
}

// ---------------------------------------------------------------------------
// GEMM (R10 config — best measured): h = relu(x @ W1 + b1)
// ---------------------------------------------------------------------------
#define A_WORDS (128 * 36)
#define B_WORDS (16 * 264)
#define STAGE_WORDS (A_WORDS + B_WORDS)
#define GEMM_SMEM (2 * STAGE_WORDS * 4)

__global__ __launch_bounds__(256, 2)
void hmma_gemm(const float* __restrict__ A, const float* __restrict__ W,
               const float* __restrict__ bias, float* __restrict__ C,
               int K, int relu)
{
    extern __shared__ uint32_t sm[];
    const uint32_t sbase = smem_u32(sm);

    const int t   = threadIdx.x;
    const int wid = t >> 5;
    const int lid = t & 31;
    const int g   = lid >> 2;
    const int t4  = lid & 3;
    const int wm  = wid & 3;
    const int wn  = wid >> 2;

    const int m0 = blockIdx.y * 128;
    const int n0 = blockIdx.x * 128;

    const int aRow = t >> 1;
    const int aP8  = (t & 1) * 8;
    const float* Ag = A + (size_t)(m0 + aRow) * K + aP8 * 2;
    const int bP = t >> 4;
    const int bN = (t & 15) * 8;
    const float* Bg = W + (size_t)(2 * bP) * HH + n0 + bN;

    const uint32_t aSts = sbase + (uint32_t)(aRow * 36 + aP8) * 4u;
    const uint32_t bSts = sbase + (uint32_t)(A_WORDS + bP * 264 + bN) * 4u;

    float acc[2][8][4];
#pragma unroll
    for (int i = 0; i < 2; i++)
#pragma unroll
        for (int j = 0; j < 8; j++)
#pragma unroll
            for (int q = 0; q < 4; q++) acc[i][j][q] = 0.0f;

    const int NC = K / 32;

    float4 ra[4], rb0[2], rb1[2];
#pragma unroll
    for (int q = 0; q < 4; q++) ra[q] = *(const float4*)(Ag + 4 * q);
#pragma unroll
    for (int q = 0; q < 2; q++) {
        rb0[q] = *(const float4*)(Bg + 4 * q);
        rb1[q] = *(const float4*)(Bg + HH + 4 * q);
    }

    for (int c = 0; c < NC; c++) {
        const uint32_t soff = (uint32_t)((c & 1) * STAGE_WORDS) * 4u;

        {
            const float* af = (const float*)ra;
            uint32_t hi[8], lo[8];
#pragma unroll
            for (int j = 0; j < 8; j++)
                h2_split(af[2 * j], af[2 * j + 1], hi[j], lo[j]);
            sts_v4(aSts + soff,      hi[0], hi[1], hi[2], hi[3]);
            sts_v4(aSts + soff + 16, hi[4], hi[5], hi[6], hi[7]);
            sts_v4(aSts + soff + 64, lo[0], lo[1], lo[2], lo[3]);
            sts_v4(aSts + soff + 80, lo[4], lo[5], lo[6], lo[7]);

            const float* b0f = (const float*)rb0;
            const float* b1f = (const float*)rb1;
#pragma unroll
            for (int j = 0; j < 8; j++)
                h2_split(b0f[j], b1f[j], hi[j], lo[j]);
            sts_v4(bSts + soff,       hi[0], hi[1], hi[2], hi[3]);
            sts_v4(bSts + soff + 16,  hi[4], hi[5], hi[6], hi[7]);
            sts_v4(bSts + soff + 528, lo[0], lo[1], lo[2], lo[3]);
            sts_v4(bSts + soff + 544, lo[4], lo[5], lo[6], lo[7]);
        }
        __syncthreads();

        if (c + 1 < NC) {
            const float* ap = Ag + (size_t)(c + 1) * 32;
#pragma unroll
            for (int q = 0; q < 4; q++) ra[q] = *(const float4*)(ap + 4 * q);
            const float* bp = Bg + (size_t)(c + 1) * 32 * HH;
#pragma unroll
            for (int q = 0; q < 2; q++) {
                rb0[q] = *(const float4*)(bp + 4 * q);
                rb1[q] = *(const float4*)(bp + HH + 4 * q);
            }
        }

        const uint32_t sA = sbase + soff;
        const uint32_t sB = sbase + soff + A_WORDS * 4u;

#pragma unroll
        for (int ks = 0; ks < 2; ks++) {
            uint32_t Ahi[2][4], Alo[2][4];
#pragma unroll
            for (int mt = 0; mt < 2; mt++) {
                const uint32_t r0 = (uint32_t)(wm * 32 + mt * 16 + g) * 36u;
                const uint32_t r8 = r0 + 8u * 36u;
                const uint32_t p  = (uint32_t)(8 * ks + t4);
                Ahi[mt][0] = lds_u32(sA + (r0 + p) * 4u);
                Ahi[mt][1] = lds_u32(sA + (r8 + p) * 4u);
                Ahi[mt][2] = lds_u32(sA + (r0 + p + 4u) * 4u);
                Ahi[mt][3] = lds_u32(sA + (r8 + p + 4u) * 4u);
                Alo[mt][0] = lds_u32(sA + (r0 + p + 16u) * 4u);
                Alo[mt][1] = lds_u32(sA + (r8 + p + 16u) * 4u);
                Alo[mt][2] = lds_u32(sA + (r0 + p + 20u) * 4u);
                Alo[mt][3] = lds_u32(sA + (r8 + p + 20u) * 4u);
            }
            const uint32_t pr0 = (uint32_t)(8 * ks + t4) * 264u;
            const uint32_t pr1 = pr0 + 4u * 264u;
#pragma unroll
            for (int nt = 0; nt < 8; nt++) {
                const uint32_t n = (uint32_t)(wn * 64 + nt * 8 + g);
                uint32_t bh0 = lds_u32(sB + (pr0 + n) * 4u);
                uint32_t bh1 = lds_u32(sB + (pr1 + n) * 4u);
                uint32_t bl0 = lds_u32(sB + (pr0 + 132u + n) * 4u);
                uint32_t bl1 = lds_u32(sB + (pr1 + 132u + n) * 4u);
#pragma unroll
                for (int mt = 0; mt < 2; mt++) {
                    mma_f16(acc[mt][nt], Ahi[mt], bh0, bh1);
                    mma_f16(acc[mt][nt], Alo[mt], bh0, bh1);
                    mma_f16(acc[mt][nt], Ahi[mt], bl0, bl1);
                }
            }
        }
        __syncthreads();
    }

#pragma unroll
    for (int mt = 0; mt < 2; mt++) {
        int row = m0 + wm * 32 + mt * 16 + g;
#pragma unroll
        for (int nt = 0; nt < 8; nt++) {
            int col = n0 + wn * 64 + nt * 8 + 2 * t4;
            float2 bv = *(const float2*)(bias + col);
            float v0 = acc[mt][nt][0] + bv.x;
            float v1 = acc[mt][nt][1] + bv.y;
            float v2 = acc[mt][nt][2] + bv.x;
            float v3 = acc[mt][nt][3] + bv.y;
            if (relu) {
                v0 = fmaxf(v0, 0.f); v1 = fmaxf(v1, 0.f);
                v2 = fmaxf(v2, 0.f); v3 = fmaxf(v3, 0.f);
            }
            *(float2*)(C + (size_t)row * HH + col) = make_float2(v0, v1);
            *(float2*)(C + (size_t)(row + 8) * HH + col) = make_float2(v2, v3);
        }
    }
}

// ---------------------------------------------------------------------------
__global__ void reset_kernel() { g_fb_count = 0; }

// ---------------------------------------------------------------------------
// Wc = W2 @ Ws  [2048 x 48]
// ---------------------------------------------------------------------------
__global__ __launch_bounds__(256, 4)
void wc_kernel(const float* __restrict__ W2, const float* __restrict__ Ws)
{
    __shared__ float es[16][128];
    __shared__ float ws[128][48];

    int r0 = blockIdx.x * 16;
    int t  = threadIdx.x;
    int r  = t >> 4;
    int c  = t & 15;

    float a0 = 0.f, a1 = 0.f, a2 = 0.f;

    for (int k0 = 0; k0 < HH; k0 += 128) {
        for (int i = t; i < 512; i += 256) {
            int rr = i >> 5, cc = (i & 31) << 2;
            *(float4*)&es[rr][cc] =
                *(const float4*)(W2 + (size_t)(r0 + rr) * HH + k0 + cc);
        }
        for (int i = t; i < 1536; i += 256) {
            int rr = i / 12, cc = (i % 12) << 2;
            *(float4*)&ws[rr][cc] = *(const float4*)(Ws + (size_t)(k0 + rr) * 48 + cc);
        }
        __syncthreads();
        float p0 = 0.f, p1 = 0.f, p2 = 0.f;
#pragma unroll 4
        for (int k = 0; k < 128; k++) {
            float e = es[r][k];
            p0 = fmaf(e, ws[k][c],      p0);
            p1 = fmaf(e, ws[k][c + 16], p1);
            p2 = fmaf(e, ws[k][c + 32], p2);
        }
        a0 += p0; a1 += p1; a2 += p2;
        __syncthreads();
    }

    g_wc[(size_t)(r0 + r) * 48 + c]      = a0;
    g_wc[(size_t)(r0 + r) * 48 + c + 16] = a1;
    g_wc[(size_t)(r0 + r) * 48 + c + 32] = a2;
}

// bc = b2 @ Ws + bs
__global__ __launch_bounds__(256, 4)
void bc_kernel(const float* __restrict__ b2, const float* __restrict__ Ws,
               const float* __restrict__ bs)
{
    __shared__ float red[256];
    int j = blockIdx.x;
    int t = threadIdx.x;
    float a = 0.f;
    for (int k = t; k < HH; k += 256)
        a = fmaf(b2[k], Ws[(size_t)k * 48 + j], a);
    red[t] = a;
    __syncthreads();
    for (int s = 128; s > 0; s >>= 1) {
        if (t < s) red[t] += red[t + s];
        __syncthreads();
    }
    if (t == 0) g_bc[j] = red[0] + bs[j];
}

// ---------------------------------------------------------------------------
// logits = g_h @ g_wc + g_bc ; argmax -> g_idx ; near-ties flagged
// ---------------------------------------------------------------------------
__global__ __launch_bounds__(256, 4)
void logits_argmax_kernel(float* __restrict__ out_logits, int write_logits)
{
    __shared__ float es[16][128];
    __shared__ float ws[128][48];
    __shared__ float ls[16][48];
    __shared__ int   sflag[16];

    int b0 = blockIdx.x * 16;
    int t  = threadIdx.x;
    int r  = t >> 4;
    int c  = t & 15;

    if (t < 16) sflag[t] = 0;

    float acc0 = 0.f, acc1 = 0.f, acc2 = 0.f;

    for (int k0 = 0; k0 < HH; k0 += 128) {
        for (int i = t; i < 512; i += 256) {
            int rr = i >> 5, cc = (i & 31) << 2;
            *(float4*)&es[rr][cc] =
                *(const float4*)(g_h + (size_t)(b0 + rr) * HH + k0 + cc);
        }
        for (int i = t; i < 1536; i += 256) {
            int rr = i / 12, cc = (i % 12) << 2;
            *(float4*)&ws[rr][cc] = *(const float4*)(g_wc + (size_t)(k0 + rr) * 48 + cc);
        }
        __syncthreads();
        float p0 = 0.f, p1 = 0.f, p2 = 0.f;
#pragma unroll 4
        for (int k = 0; k < 128; k++) {
            float e = es[r][k];
            p0 = fmaf(e, ws[k][c],      p0);
            p1 = fmaf(e, ws[k][c + 16], p1);
            p2 = fmaf(e, ws[k][c + 32], p2);
        }
        acc0 += p0; acc1 += p1; acc2 += p2;
        __syncthreads();
    }

    ls[r][c]      = acc0 + g_bc[c];
    ls[r][c + 16] = acc1 + g_bc[c + 16];
    ls[r][c + 32] = acc2 + g_bc[c + 32];
    __syncthreads();

    if (write_logits) {
        for (int i = t; i < 16 * 48; i += 256) {
            int rr = i / 48, cc = i % 48;
            out_logits[(size_t)(b0 + rr) * 48 + cc] = ls[rr][cc];
        }
    }
    if (t < 128) {
        int rr = t >> 3, tt = t & 7;
        const float* lp = &ls[rr][tt * 6];
        float best = lp[0], second = -3.4e38f;
        int bi = 0;
#pragma unroll
        for (int m = 1; m < 6; m++) {
            float v = lp[m];
            if (v > best) { second = best; best = v; bi = m; }
            else if (v > second) second = v;
        }
        g_idx[(b0 + rr) * TT + tt] = bi;
        if (best - second < GAP_THR) sflag[rr] = 1;
    }
    __syncthreads();
    if (t < 16 && sflag[t]) {
        int pos = atomicAdd(&g_fb_count, 1);
        g_fb_list[pos] = b0 + t;
    }
}

// ---------------------------------------------------------------------------
// Batched exact fp32 fallback:
//   gather flagged x rows -> g_xf, then two fp32 SGEMMs + logits/argmax.
// ---------------------------------------------------------------------------
__global__ __launch_bounds__(256, 4)
void gather_xf(const float* __restrict__ x)
{
    int s = blockIdx.x;
    int total = g_fb_count; if (total > FBM) total = FBM;
    if (s >= total) return;
    const float4* src = (const float4*)(x + (size_t)g_fb_list[s] * DD);
    float4* dst = (float4*)(g_xf + (size_t)s * DD);
    for (int i = threadIdx.x; i < DD / 4; i += 256) dst[i] = src[i];
}

// fp32 SGEMM (R1-proven structure): C[M=grid.y*128, N=2048] = op(A@W + bias)
__global__ __launch_bounds__(256, 2)
void sgemm_fb(const float* __restrict__ A, const float* __restrict__ Bm,
              const float* __restrict__ bias, float* __restrict__ C,
              int K, int relu)
{
    __shared__ float As[8][128];
    __shared__ float Bs[8][128];

    const int N = HH;
    int bx = blockIdx.x;
    int by = blockIdx.y;
    int t  = threadIdx.x;
    int tx = t & 15;
    int ty = t >> 4;

    const float* Ag = A + (size_t)(by * 128) * K;
    const float* Bg = Bm + (size_t)(bx * 128);

    float acc[8][8];
#pragma unroll
    for (int i = 0; i < 8; i++)
#pragma unroll
        for (int j = 0; j < 8; j++) acc[i][j] = 0.0f;

    int aRow = t >> 1;
    int aCol = (t & 1) * 4;
    int bRow = t >> 5;
    int bCol = (t & 31) * 4;

    for (int k0 = 0; k0 < K; k0 += 8) {
        float4 av = *(const float4*)(Ag + (size_t)aRow * K + k0 + aCol);
        As[aCol + 0][aRow] = av.x;
        As[aCol + 1][aRow] = av.y;
        As[aCol + 2][aRow] = av.z;
        As[aCol + 3][aRow] = av.w;
        float4 bv = *(const float4*)(Bg + (size_t)(k0 + bRow) * N + bCol);
        *(float4*)&Bs[bRow][bCol] = bv;
        __syncthreads();

#pragma unroll
        for (int kk = 0; kk < 8; kk++) {
            float ar[8], br[8];
#pragma unroll
            for (int i = 0; i < 8; i++) ar[i] = As[kk][ty * 8 + i];
#pragma unroll
            for (int j = 0; j < 8; j++) br[j] = Bs[kk][tx * 8 + j];
#pragma unroll
            for (int i = 0; i < 8; i++)
#pragma unroll
                for (int j = 0; j < 8; j++)
                    acc[i][j] = fmaf(ar[i], br[j], acc[i][j]);
        }
        __syncthreads();
    }

#pragma unroll
    for (int i = 0; i < 8; i++) {
        int row = by * 128 + ty * 8 + i;
        float* crow = C + (size_t)row * N + bx * 128 + tx * 8;
#pragma unroll
        for (int j4 = 0; j4 < 2; j4++) {
            int col = bx * 128 + tx * 8 + j4 * 4;
            float4 v;
            v.x = acc[i][j4 * 4 + 0] + bias[col + 0];
            v.y = acc[i][j4 * 4 + 1] + bias[col + 1];
            v.z = acc[i][j4 * 4 + 2] + bias[col + 2];
            v.w = acc[i][j4 * 4 + 3] + bias[col + 3];
            if (relu) {
                v.x = fmaxf(v.x, 0.f); v.y = fmaxf(v.y, 0.f);
                v.z = fmaxf(v.z, 0.f); v.w = fmaxf(v.w, 0.f);
            }
            *(float4*)(crow + j4 * 4) = v;
        }
    }
}

// logits + argmax for flagged samples, k split 4 ways
__global__ __launch_bounds__(192, 4)
void fb_l_kernel(const float* __restrict__ Ws, const float* __restrict__ bs)
{
    __shared__ float part[48][4];
    __shared__ float ls[48];
    int total = g_fb_count; if (total > FBM) total = FBM;
    const int t = threadIdx.x;
    const int j  = t >> 2;
    const int kp = t & 3;

    for (int s = blockIdx.x; s < total; s += gridDim.x) {
        const float* ep = g_ef + (size_t)s * HH;
        float a = 0.f;
        const int k0 = kp * 512;
        for (int k = k0; k < k0 + 512; k++)
            a = fmaf(ep[k], Ws[(size_t)k * 48 + j], a);
        part[j][kp] = a;
        __syncthreads();
        if (t < 48)
            ls[t] = part[t][0] + part[t][1] + part[t][2] + part[t][3] + bs[t];
        __syncthreads();
        if (t < 8) {
            const float* lp = &ls[t * 6];
            float best = lp[0]; int bi = 0;
#pragma unroll
            for (int m = 1; m < 6; m++) {
                float v = lp[m];
                if (v > best) { best = v; bi = m; }
            }
            g_idx[g_fb_list[s] * TT + t] = bi;
        }
        __syncthreads();
    }
}

// ---------------------------------------------------------------------------
// Bitonic sort of rows [b_off, b_off+grid) of x -> g_xs
// ---------------------------------------------------------------------------
__global__ __launch_bounds__(1024, 2)
void sort_rows_kernel(const float* __restrict__ x, int b_off)
{
    __shared__ float s[4096];
    int b = blockIdx.x + b_off;
    const float* xp = x + (size_t)b * DD;
    for (int i = threadIdx.x; i < 4096; i += 1024) s[i] = xp[i];
    __syncthreads();

    for (int k = 2; k <= 4096; k <<= 1) {
        for (int j = k >> 1; j > 0; j >>= 1) {
#pragma unroll
            for (int base = 0; base < 4096; base += 1024) {
                int i   = base + threadIdx.x;
                int ixj = i ^ j;
                if (ixj > i) {
                    bool asc = ((i & k) == 0);
                    float a = s[i], bb = s[ixj];
                    if ((a > bb) == asc) { s[i] = bb; s[ixj] = a; }
                }
            }
            __syncthreads();
        }
    }
    float* op = g_xs + (size_t)b * DD;
    for (int i = threadIdx.x; i < 4096; i += 1024) op[i] = s[i];
}

// ---------------------------------------------------------------------------
// Collapsed scan + emit: outputs[b,t,:] = a_t * perm_t(x_b) + c_t
// ---------------------------------------------------------------------------
__global__ __launch_bounds__(512, 4)
void emit_kernel(const float* __restrict__ x,
                 const float* __restrict__ add_s, const float* __restrict__ sub_s,
                 const float* __restrict__ mul_s, const float* __restrict__ div_s,
                 float* __restrict__ out)
{
    __shared__ float sa[8], sb[8];
    __shared__ int   sm8[8];
    int b = blockIdx.x;

    if (threadIdx.x == 0) {
        float A = 1.0f, Bc = 0.0f;
        int mode = 0;
        float ad = *add_s, su = *sub_s, mu = *mul_s;
        float dv = *div_s + 1e-5f;
#pragma unroll
        for (int t = 0; t < 8; t++) {
            int m = g_idx[b * 8 + t];
            switch (m) {
                case 0: mode = 2;              break;
                case 1: mode ^= 1;             break;
                case 2: Bc += ad;              break;
                case 3: Bc -= su;              break;
                case 4: A *= mu; Bc *= mu;     break;
                case 5: A /= dv; Bc /= dv;     break;
            }
            sa[t] = A; sb[t] = Bc; sm8[t] = mode;
        }
    }
    __syncthreads();

    const float4* xr  = (const float4*)(x    + (size_t)b * DD);
    const float4* xsr = (const float4*)(g_xs + (size_t)b * DD);
    float* ob = out + (size_t)b * ((size_t)TT * DD);
    const int Q = DD / 4;

#pragma unroll 1
    for (int t = 0; t < 8; t++) {
        float A = sa[t], Bc = sb[t];
        int mode = sm8[t];
        const float4* src = (mode & 2) ? xsr : xr;
        bool rev = (mode & 1);
        float4* op = (float4*)(ob + (size_t)t * DD);
#pragma unroll
        for (int u = 0; u < 2; u++) {
            int i = threadIdx.x + 512 * u;
            float4 v;
            if (!rev) {
                v = src[i];
            } else {
                float4 w = src[Q - 1 - i];
                v.x = w.w; v.y = w.z; v.z = w.y; v.w = w.x;
            }
            v.x = fmaf(A, v.x, Bc);
            v.y = fmaf(A, v.y, Bc);
            v.z = fmaf(A, v.z, Bc);
            v.w = fmaf(A, v.w, Bc);
            stg_cs(&op[i], v);
        }
    }
}

// ---------------------------------------------------------------------------
extern "C" void kernel_launch(void* const* d_in, const int* in_sizes, int n_in,
                              void* d_out, int out_size)
{
    const float* x     = (const float*)d_in[0];
    const float* W1    = (const float*)d_in[1];
    const float* b1    = (const float*)d_in[2];
    const float* W2    = (const float*)d_in[3];
    const float* b2    = (const float*)d_in[4];
    const float* Ws    = (const float*)d_in[5];
    const float* bs    = (const float*)d_in[6];
    const float* add_s = (const float*)d_in[7];
    const float* sub_s = (const float*)d_in[8];
    const float* mul_s = (const float*)d_in[9];
    const float* div_s = (const float*)d_in[10];
    float* out = (float*)d_out;

    const size_t out_main = (size_t)BB * TT * DD;
    const size_t out_need = out_main + (size_t)BB * TT * MM;
    int write_logits = ((size_t)out_size >= out_need) ? 1 : 0;
    float* out_logits = out + out_main;

    static cudaStream_t s_aux = nullptr;
    static cudaEvent_t ev_fork = nullptr, ev_aux1 = nullptr;
    if (s_aux == nullptr) {
        cudaStreamCreateWithFlags(&s_aux, cudaStreamNonBlocking);
        cudaEventCreateWithFlags(&ev_fork, cudaEventDisableTiming);
        cudaEventCreateWithFlags(&ev_aux1, cudaEventDisableTiming);
        cudaFuncSetAttribute(hmma_gemm, cudaFuncAttributeMaxDynamicSharedMemorySize, GEMM_SMEM);
    }

    float* d_gh;  cudaGetSymbolAddress((void**)&d_gh,  g_h);
    float* d_xf;  cudaGetSymbolAddress((void**)&d_xf,  g_xf);
    float* d_hf;  cudaGetSymbolAddress((void**)&d_hf,  g_hf);
    float* d_ef;  cudaGetSymbolAddress((void**)&d_ef,  g_ef);

    // main: reset -> fork
    reset_kernel<<<1, 1>>>();
    cudaEventRecord(ev_fork, 0);
    cudaStreamWaitEvent(s_aux, ev_fork, 0);

    // aux: sorts + wc + bc (concurrent with gemm1)
    sort_rows_kernel<<<BB / 2, 1024, 0, s_aux>>>(x, 0);
    sort_rows_kernel<<<BB / 2, 1024, 0, s_aux>>>(x, BB / 2);
    wc_kernel<<<HH / 16, 256, 0, s_aux>>>(W2, Ws);
    bc_kernel<<<48, 256, 0, s_aux>>>(b2, Ws, bs);
    cudaEventRecord(ev_aux1, s_aux);

    // main: gemm1
    dim3 g(HH / 128, BB / 128);
    hmma_gemm<<<g, 256, GEMM_SMEM>>>(x, W1, b1, d_gh, DD, 1);

    // main waits for aux prep, then logits
    cudaStreamWaitEvent(0, ev_aux1, 0);
    logits_argmax_kernel<<<BB / 16, 256>>>(out_logits, write_logits);

    // batched exact fp32 fallback
    gather_xf<<<FBM, 256>>>(x);
    dim3 gf(HH / 128, FBM / 128);   // (16, 2)
    sgemm_fb<<<gf, 256>>>(d_xf, W1, b1, d_hf, DD, 1);
    sgemm_fb<<<gf, 256>>>(d_hf, W2, b2, d_ef, HH, 0);
    fb_l_kernel<<<FBM, 192>>>(Ws, bs);

    // emit with final routing
    emit_kernel<<<BB, 512>>>(x, add_s, sub_s, mul_s, div_s, out);
}